// round 17
// baseline (speedup 1.0000x reference)
#include <cuda_runtime.h>
#include <cuda_bf16.h>

// out[b,s,e] = W_e[e, tokens[b,s]] + W_p[s,e]
// tokens: (2,2048) int32, W_e: (1024,32000) f32, W_p: (2048,1024) f32
// out: (2,2048,1024) f32
//
// Streaming v11: big-tile DMA pipeline.
// R15 (ET=16, 2 buf, 6 blk/SM): 27.6us @ 5.36TB/s, in-flight ~32KB/block at
// the wait point. R16 (ET=8, depth 3) REDUCED in-flight to 24KB -> 4.6TB/s,
// confirming the stream is in-flight-bytes limited. v11 turns the knob up:
// ET=32 (32KB tiles), double-buffered, dynamic smem 68.6KB -> 3 blocks/SM,
// grid = 125 bins x 3 = 375 (single wave). In-flight 64KB/block = 192KB/SM
// (2x R15). Per-tile barrier/epilogue overhead halves; scan redundancy
// drops to 375x4096.

#define B 2
#define S 2048
#define E 1024
#define V 32000
#define NTOK (B * S)       // 4096

#define V_TILE 256
#define NBINS (V / V_TILE) // 125
#define ET 32              // e-rows per subtile (32KB tiles)
#define KPB 3              // blocks per bin -> grid 375 (single wave @ 3/SM)
#define SSTRIDE 260        // rows 1040B apart; 16B-aligned bulk dst
#define CAP 512            // hit-list capacity (bin avg ~33; fallback if over)
#define TILE_BYTES (ET * V_TILE * 4)        // 32768
#define TILE_FLOATS (ET * SSTRIDE)          // 8320
#define SMEM_BYTES (2 * TILE_FLOATS * 4 + CAP * 4 + 64)

__global__ __launch_bounds__(256)
void embed_kernel(const int* __restrict__ tokens,
                  const float* __restrict__ W_e,
                  const float* __restrict__ W_p,
                  float* __restrict__ out) {
    extern __shared__ __align__(16) float smem[];
    float* tile0 = smem;                        // 33280B
    float* tile1 = smem + TILE_FLOATS;          // 33280B
    int*   list  = (int*)(smem + 2 * TILE_FLOATS);          // 2KB
    unsigned long long* mbar = (unsigned long long*)(list + CAP);
    int*   s_cnt = (int*)(mbar + 2);

    int bin = blockIdx.x % NBINS;
    int k   = blockIdx.x / NBINS;               // 0..2
    int nt  = (k < 2) ? 11 : 10;                // 32 tiles split 11+11+10
    int t0  = (k < 2) ? 11 * k : 22;
    int v0  = bin << 8;
    int tid = threadIdx.x;

    float* tiles[2] = {tile0, tile1};
    unsigned mb0 = (unsigned)__cvta_generic_to_shared(&mbar[0]);
    unsigned mb1 = (unsigned)__cvta_generic_to_shared(&mbar[1]);

    if (tid == 0) {
        *s_cnt = 0;
        asm volatile("mbarrier.init.shared.b64 [%0], 1;" :: "r"(mb0));
        asm volatile("mbarrier.init.shared.b64 [%0], 1;" :: "r"(mb1));
        asm volatile("fence.proxy.async.shared::cta;" ::: "memory");
    }
    __syncthreads();                            // init + s_cnt visible

    // ---- Issue tile 0: 32 bulk 1KB row-copies, one thread.
    if (tid == 0) {
        asm volatile("mbarrier.arrive.expect_tx.shared.b64 _, [%0], %1;"
                     :: "r"(mb0), "r"(TILE_BYTES));
#pragma unroll
        for (int r = 0; r < ET; r++) {
            const float* src = W_e + (size_t)(t0 * ET + r) * V + v0;
            unsigned dst = (unsigned)__cvta_generic_to_shared(&tile0[r * SSTRIDE]);
            asm volatile(
                "cp.async.bulk.shared::cta.global.mbarrier::complete_tx::bytes"
                " [%0], [%1], %2, [%3];"
                :: "r"(dst), "l"(src), "r"(V_TILE * 4), "r"(mb0) : "memory");
        }
    }

    // ---- Scan: compact this bin's tokens (hidden under the tile-0 fetch).
#pragma unroll
    for (int i = 0; i < 4; i++) {
        int4 tv = __ldg(reinterpret_cast<const int4*>(tokens) + tid + 256 * i);
        int tk0 = (tid + 256 * i) * 4;
        int vv[4] = {tv.x, tv.y, tv.z, tv.w};
#pragma unroll
        for (int kk = 0; kk < 4; kk++) {
            if ((vv[kk] >> 8) == bin) {
                int pos = atomicAdd(s_cnt, 1);
                if (pos < CAP) list[pos] = ((tk0 + kk) << 8) | (vv[kk] & 255);
            }
        }
    }
    __syncthreads();
    int total = *s_cnt;

    if (total <= CAP) {
        int j  = tid & 7;                       // float4 slot (32 floats/row)
        int hb = tid >> 3;                      // 32 tokens per pass
        for (int t = 0; t < nt; t++) {
            // Issue tile t+1 into the other buffer (drained before the
            // previous iteration's closing __syncthreads).
            if (t < nt - 1 && tid == 0) {
                unsigned mb = ((t + 1) & 1) ? mb1 : mb0;
                float* buf = tiles[(t + 1) & 1];
                asm volatile("mbarrier.arrive.expect_tx.shared.b64 _, [%0], %1;"
                             :: "r"(mb), "r"(TILE_BYTES));
#pragma unroll
                for (int r = 0; r < ET; r++) {
                    const float* src = W_e + (size_t)((t0 + t + 1) * ET + r) * V + v0;
                    unsigned dst = (unsigned)__cvta_generic_to_shared(&buf[r * SSTRIDE]);
                    asm volatile(
                        "cp.async.bulk.shared::cta.global.mbarrier::complete_tx::bytes"
                        " [%0], [%1], %2, [%3];"
                        :: "r"(dst), "l"(src), "r"(V_TILE * 4), "r"(mb) : "memory");
                }
            }

            // Wait tile t: buffer t&1, phase (t>>1)&1 (HW-sleep try_wait).
            {
                unsigned mbw = (t & 1) ? mb1 : mb0;
                unsigned ph  = (t >> 1) & 1;
                unsigned done;
                asm volatile(
                    "{\n\t.reg .pred p;\n\t"
                    "mbarrier.try_wait.parity.shared.b64 p, [%1], %2;\n\t"
                    "selp.b32 %0, 1, 0, p;\n\t}"
                    : "=r"(done) : "r"(mbw), "r"(ph) : "memory");
                while (!done) {
                    asm volatile(
                        "{\n\t.reg .pred p;\n\t"
                        "mbarrier.try_wait.parity.shared.b64 p, [%1], %2, 0x989680;\n\t"
                        "selp.b32 %0, 1, 0, p;\n\t}"
                        : "=r"(done) : "r"(mbw), "r"(ph) : "memory");
                }
            }

            const float* tl = tiles[t & 1];
            int e0 = (t0 + t) * ET;
            for (int h = hb; h < total; h += 32) {
                int packed = list[h];
                int tk = packed >> 8;
                int vl = packed & 255;
                int s  = tk & (S - 1);
                float4 p = __ldg(reinterpret_cast<const float4*>(
                    W_p + (size_t)s * E + e0) + j);
                float4 r;
                r.x = tl[(4 * j + 0) * SSTRIDE + vl] + p.x;
                r.y = tl[(4 * j + 1) * SSTRIDE + vl] + p.y;
                r.z = tl[(4 * j + 2) * SSTRIDE + vl] + p.z;
                r.w = tl[(4 * j + 3) * SSTRIDE + vl] + p.w;
                __stcs(reinterpret_cast<float4*>(out + (size_t)tk * E + e0) + j, r);
            }
            __syncthreads();   // buffer t fully drained before its reissue
        }
    } else {
        // ---- Fallback (pathological token skew; never hit by this input).
        // Uses tile1 for staging; the orphaned tile-0 bulk copy writes tile0
        // harmlessly.
        __syncthreads();
        for (int t = 0; t < nt; t++) {
            int row0 = (t0 + t) * ET;
#pragma unroll
            for (int i = 0; i < 8; i++) {
                int idx = tid + 256 * i;
                int r = idx >> 6, c = idx & 63;
                float4 val = __ldg(reinterpret_cast<const float4*>(
                    W_e + (size_t)(row0 + r) * V + v0) + c);
                *reinterpret_cast<float4*>(&tile1[r * SSTRIDE + 4 * c]) = val;
            }
            __syncthreads();
            for (int idx = tid; idx < NTOK; idx += 256) {
                int v = __ldg(&tokens[idx]);
                if ((v >> 8) == bin) {
                    int vl = v & 255;
                    int s  = idx & (S - 1);
                    for (int rr = 0; rr < ET; rr++)
                        out[(size_t)idx * E + row0 + rr] =
                            tile1[rr * SSTRIDE + vl] + W_p[(size_t)s * E + row0 + rr];
                }
            }
            __syncthreads();
        }
    }
}

extern "C" void kernel_launch(void* const* d_in, const int* in_sizes, int n_in,
                              void* d_out, int out_size) {
    const int*   tokens = (const int*)d_in[0];
    const float* W_e    = (const float*)d_in[1];
    const float* W_p    = (const float*)d_in[2];
    float*       out    = (float*)d_out;

    static bool attr_set = false;
    if (!attr_set) {
        cudaFuncSetAttribute(embed_kernel,
                             cudaFuncAttributeMaxDynamicSharedMemorySize,
                             SMEM_BYTES);
        attr_set = true;
    }
    embed_kernel<<<NBINS * KPB, 256, SMEM_BYTES>>>(tokens, W_e, W_p, out);
}